// round 4
// baseline (speedup 1.0000x reference)
#include <cuda_runtime.h>
#include <math.h>

// Problem shape (fixed by the dataset)
#define N_NODES 100000
#define N_EDGES 3200000
#define LATENT  64            // floats per row
#define D2      (LATENT/2)    // float2 per row = 32 (one per lane)

// ---------------- scratch (no allocs allowed) ----------------
__device__ int   g_deg[N_NODES];
__device__ int   g_fill[N_NODES];
__device__ int   g_rowptr[N_NODES + 1];
__device__ int2  g_cv[N_EDGES];             // .x = col, .y = val (bitcast float)
__device__ float g_tmp[N_NODES * LATENT];   // result of first hop

// ---------------- CSR build ----------------
__global__ void zero_counts_kernel() {
    int i = blockIdx.x * blockDim.x + threadIdx.x;
    if (i < N_NODES) { g_deg[i] = 0; g_fill[i] = 0; }
}

__global__ void histogram_kernel(const int* __restrict__ rows) {
    int i = blockIdx.x * blockDim.x + threadIdx.x;
    int stride = gridDim.x * blockDim.x;
    for (int e = i; e < N_EDGES; e += stride)
        atomicAdd(&g_deg[rows[e]], 1);
}

// single-block exclusive scan of g_deg -> g_rowptr (N=100k, 1024 threads).
// Threads whose range clamps to empty still participate in the block scan and
// (for t near the end) redundantly write g_rowptr[N] = N_EDGES — benign.
__global__ void scan_kernel() {
    __shared__ int sums[1024];
    const int t = threadIdx.x;
    const int chunk = (N_NODES + 1023) / 1024;   // 98
    int start = t * chunk;
    int end   = start + chunk; if (end > N_NODES) end = N_NODES;
    if (start > N_NODES) start = N_NODES;

    int s = 0;
    for (int i = start; i < end; i++) s += g_deg[i];
    sums[t] = s;
    __syncthreads();
    for (int off = 1; off < 1024; off <<= 1) {
        int v = (t >= off) ? sums[t - off] : 0;
        __syncthreads();
        sums[t] += v;
        __syncthreads();
    }
    int run = (t == 0) ? 0 : sums[t - 1];
    for (int i = start; i < end; i++) {
        g_rowptr[i] = run;
        run += g_deg[i];
    }
    if (end == N_NODES) g_rowptr[N_NODES] = run;   // == N_EDGES
}

__global__ void scatter_kernel(const int* __restrict__ rows,
                               const int* __restrict__ cols,
                               const float* __restrict__ vals) {
    int i = blockIdx.x * blockDim.x + threadIdx.x;
    int stride = gridDim.x * blockDim.x;
    for (int e = i; e < N_EDGES; e += stride) {
        int r = rows[e];
        int pos = g_rowptr[r] + atomicAdd(&g_fill[r], 1);
        int2 cv; cv.x = cols[e]; cv.y = __float_as_int(vals[e]);
        g_cv[pos] = cv;
    }
}

// ---------------- SpMM: warp per row, lane holds float2 (2 of 64 cols) ----------------
__device__ __forceinline__ float2 spmm_row(int row, int lane,
                                           const float* __restrict__ src) {
    const int s = g_rowptr[row];
    const int e = g_rowptr[row + 1];
    float2 acc = make_float2(0.f, 0.f);
    const float2* __restrict__ src2 = reinterpret_cast<const float2*>(src);

    int b = s;
    // full 32-edge batches: no per-lane masking, unroll 8 for gather MLP
    for (; b + 32 <= e; b += 32) {
        int2 cv = __ldg(&g_cv[b + lane]);
        #pragma unroll 8
        for (int j = 0; j < 32; j++) {
            int   cj = __shfl_sync(0xffffffffu, cv.x, j);
            float vj = __int_as_float(__shfl_sync(0xffffffffu, cv.y, j));
            float2 xr = __ldg(&src2[(size_t)cj * D2 + lane]);
            acc.x = fmaf(vj, xr.x, acc.x);
            acc.y = fmaf(vj, xr.y, acc.y);
        }
    }
    // tail (< 32 edges)
    if (b < e) {
        int idx = b + lane;
        int2 cv = make_int2(0, 0);
        if (idx < e) cv = __ldg(&g_cv[idx]);
        int m = e - b;
        for (int j = 0; j < m; j++) {
            int   cj = __shfl_sync(0xffffffffu, cv.x, j);
            float vj = __int_as_float(__shfl_sync(0xffffffffu, cv.y, j));
            float2 xr = __ldg(&src2[(size_t)cj * D2 + lane]);
            acc.x = fmaf(vj, xr.x, acc.x);
            acc.y = fmaf(vj, xr.y, acc.y);
        }
    }
    return acc;
}

__global__ void __launch_bounds__(256) hop1_kernel(const float* __restrict__ x) {
    int gw   = (blockIdx.x * blockDim.x + threadIdx.x) >> 5;
    int lane = threadIdx.x & 31;
    if (gw >= N_NODES) return;
    float2 acc = spmm_row(gw, lane, x);
    reinterpret_cast<float2*>(g_tmp)[(size_t)gw * D2 + lane] = acc;
}

__global__ void __launch_bounds__(256) hop2_kernel(const float* __restrict__ x,
                                                   const float* __restrict__ alpha,
                                                   float* __restrict__ out) {
    int gw   = (blockIdx.x * blockDim.x + threadIdx.x) >> 5;
    int lane = threadIdx.x & 31;
    if (gw >= N_NODES) return;
    float2 acc = spmm_row(gw, lane, g_tmp);
    float sig = 1.0f / (1.0f + __expf(-alpha[gw]));
    float2 xr = reinterpret_cast<const float2*>(x)[(size_t)gw * D2 + lane];
    float2 r;
    r.x = sig * acc.x - xr.x;
    r.y = sig * acc.y - xr.y;
    reinterpret_cast<float2*>(out)[(size_t)gw * D2 + lane] = r;
}

// ---------------- launch ----------------
extern "C" void kernel_launch(void* const* d_in, const int* in_sizes, int n_in,
                              void* d_out, int out_size) {
    // inputs (metadata order): t, x[N,64], alpha[N], edge_rows[E], edge_cols[E], edge_vals[E]
    const float* x     = (const float*)d_in[1];
    const float* alpha = (const float*)d_in[2];
    const int*   erow  = (const int*)d_in[3];
    const int*   ecol  = (const int*)d_in[4];
    const float* evals = (const float*)d_in[5];
    float* out = (float*)d_out;

    zero_counts_kernel<<<(N_NODES + 511) / 512, 512>>>();
    histogram_kernel<<<1184, 512>>>(erow);       // 148 SMs * 8 blocks/SM wave
    scan_kernel<<<1, 1024>>>();
    scatter_kernel<<<1184, 512>>>(erow, ecol, evals);

    const int threads = 256;
    const int blocks  = (N_NODES * 32 + threads - 1) / threads;  // 12500
    hop1_kernel<<<blocks, threads>>>(x);
    hop2_kernel<<<blocks, threads>>>(x, alpha, out);
}

// round 5
// speedup vs baseline: 1.0217x; 1.0217x over previous
#include <cuda_runtime.h>
#include <cuda_fp16.h>
#include <math.h>

// Problem shape (fixed by the dataset)
#define N_NODES 100000
#define N_EDGES 3200000
#define LATENT  64            // floats per row
#define H2      (LATENT/2)    // half2 per row = 32 (one per lane)

// ---------------- scratch (no allocs allowed) ----------------
__device__ int     g_deg[N_NODES];
__device__ int     g_fill[N_NODES];
__device__ int     g_rowptr[N_NODES + 1];
__device__ int2    g_cv[N_EDGES];              // .x = col, .y = val (bitcast float)
__device__ __half2 g_xh[N_NODES * H2];         // fp16-staged x
__device__ __half2 g_tmph[N_NODES * H2];       // fp16 first-hop result

// ---------------- stage x -> fp16 and zero counters (fused) ----------------
__global__ void stage_kernel(const float* __restrict__ x) {
    int i = blockIdx.x * blockDim.x + threadIdx.x;
    int stride = gridDim.x * blockDim.x;
    const float2* __restrict__ x2 = reinterpret_cast<const float2*>(x);
    for (int k = i; k < N_NODES * H2; k += stride) {
        float2 v = x2[k];
        g_xh[k] = __floats2half2_rn(v.x, v.y);
    }
    for (int k = i; k < N_NODES; k += stride) { g_deg[k] = 0; g_fill[k] = 0; }
}

__global__ void histogram_kernel(const int* __restrict__ rows) {
    int i = blockIdx.x * blockDim.x + threadIdx.x;
    int stride = gridDim.x * blockDim.x;
    for (int e = i; e < N_EDGES; e += stride)
        atomicAdd(&g_deg[rows[e]], 1);
}

// single-block exclusive scan of g_deg -> g_rowptr (N=100k, 1024 threads)
__global__ void scan_kernel() {
    __shared__ int sums[1024];
    const int t = threadIdx.x;
    const int chunk = (N_NODES + 1023) / 1024;   // 98
    int start = t * chunk;
    int end   = start + chunk; if (end > N_NODES) end = N_NODES;
    if (start > N_NODES) start = N_NODES;

    int s = 0;
    for (int i = start; i < end; i++) s += g_deg[i];
    sums[t] = s;
    __syncthreads();
    for (int off = 1; off < 1024; off <<= 1) {
        int v = (t >= off) ? sums[t - off] : 0;
        __syncthreads();
        sums[t] += v;
        __syncthreads();
    }
    int run = (t == 0) ? 0 : sums[t - 1];
    for (int i = start; i < end; i++) {
        g_rowptr[i] = run;
        run += g_deg[i];
    }
    if (end == N_NODES) g_rowptr[N_NODES] = run;   // == N_EDGES
}

__global__ void scatter_kernel(const int* __restrict__ rows,
                               const int* __restrict__ cols,
                               const float* __restrict__ vals) {
    int i = blockIdx.x * blockDim.x + threadIdx.x;
    int stride = gridDim.x * blockDim.x;
    for (int e = i; e < N_EDGES; e += stride) {
        int r = rows[e];
        int pos = g_rowptr[r] + atomicAdd(&g_fill[r], 1);
        int2 cv; cv.x = cols[e]; cv.y = __float_as_int(vals[e]);
        g_cv[pos] = cv;
    }
}

// ---------------- SpMM: warp per row, lane holds half2 (2 of 64 cols), fp32 acc ----------------
__device__ __forceinline__ float2 spmm_row_h(int row, int lane,
                                             const __half2* __restrict__ srch) {
    const int s = g_rowptr[row];
    const int e = g_rowptr[row + 1];
    float2 acc = make_float2(0.f, 0.f);

    int b = s;
    // full 32-edge batches: no per-lane masking, unroll 8 for gather MLP
    for (; b + 32 <= e; b += 32) {
        int2 cv = __ldg(&g_cv[b + lane]);
        #pragma unroll 8
        for (int j = 0; j < 32; j++) {
            int   cj = __shfl_sync(0xffffffffu, cv.x, j);
            float vj = __int_as_float(__shfl_sync(0xffffffffu, cv.y, j));
            __half2 h = __ldg(&srch[cj * H2 + lane]);
            float2 xf = __half22float2(h);
            acc.x = fmaf(vj, xf.x, acc.x);
            acc.y = fmaf(vj, xf.y, acc.y);
        }
    }
    // tail (< 32 edges)
    if (b < e) {
        int idx = b + lane;
        int2 cv = make_int2(0, 0);
        if (idx < e) cv = __ldg(&g_cv[idx]);
        int m = e - b;
        for (int j = 0; j < m; j++) {
            int   cj = __shfl_sync(0xffffffffu, cv.x, j);
            float vj = __int_as_float(__shfl_sync(0xffffffffu, cv.y, j));
            __half2 h = __ldg(&srch[cj * H2 + lane]);
            float2 xf = __half22float2(h);
            acc.x = fmaf(vj, xf.x, acc.x);
            acc.y = fmaf(vj, xf.y, acc.y);
        }
    }
    return acc;
}

__global__ void __launch_bounds__(256) hop1_kernel() {
    int gw   = (blockIdx.x * blockDim.x + threadIdx.x) >> 5;
    int lane = threadIdx.x & 31;
    if (gw >= N_NODES) return;
    float2 acc = spmm_row_h(gw, lane, g_xh);
    g_tmph[gw * H2 + lane] = __floats2half2_rn(acc.x, acc.y);
}

__global__ void __launch_bounds__(256) hop2_kernel(const float* __restrict__ x,
                                                   const float* __restrict__ alpha,
                                                   float* __restrict__ out) {
    int gw   = (blockIdx.x * blockDim.x + threadIdx.x) >> 5;
    int lane = threadIdx.x & 31;
    if (gw >= N_NODES) return;
    float2 acc = spmm_row_h(gw, lane, g_tmph);
    float sig = 1.0f / (1.0f + __expf(-alpha[gw]));
    float2 xr = reinterpret_cast<const float2*>(x)[(size_t)gw * H2 + lane];
    float2 r;
    r.x = sig * acc.x - xr.x;
    r.y = sig * acc.y - xr.y;
    reinterpret_cast<float2*>(out)[(size_t)gw * H2 + lane] = r;
}

// ---------------- launch ----------------
extern "C" void kernel_launch(void* const* d_in, const int* in_sizes, int n_in,
                              void* d_out, int out_size) {
    // inputs (metadata order): t, x[N,64], alpha[N], edge_rows[E], edge_cols[E], edge_vals[E]
    const float* x     = (const float*)d_in[1];
    const float* alpha = (const float*)d_in[2];
    const int*   erow  = (const int*)d_in[3];
    const int*   ecol  = (const int*)d_in[4];
    const float* evals = (const float*)d_in[5];
    float* out = (float*)d_out;

    stage_kernel<<<1184, 512>>>(x);                 // x -> fp16 + zero counters
    histogram_kernel<<<1184, 512>>>(erow);
    scan_kernel<<<1, 1024>>>();
    scatter_kernel<<<1184, 512>>>(erow, ecol, evals);

    const int threads = 256;
    const int blocks  = (N_NODES * 32 + threads - 1) / threads;  // 12500
    hop1_kernel<<<blocks, threads>>>();
    hop2_kernel<<<blocks, threads>>>(x, alpha, out);
}